// round 4
// baseline (speedup 1.0000x reference)
#include <cuda_runtime.h>
#include <cstdint>

#define BB 4
#define TT 2048
#define CC 576
#define HH 12
#define DD 48
#define MM (BB*TT)       /* 8192 */
#define NQKV (3*CC)      /* 1728 */

// Scratch (device globals: allocation-free). q/k/v stored pre-rounded to tf32
// (q additionally pre-scaled by 1/sqrt(48)).
__device__ float g_q[BB*HH*TT*DD];
__device__ float g_k[BB*HH*TT*DD];
__device__ float g_v[BB*HH*TT*DD];
__device__ float g_y[BB*TT*CC];

// ---------------------------------------------------------------------------
// helpers
// ---------------------------------------------------------------------------
__device__ __forceinline__ unsigned f2tf(float x) {
    unsigned r;
    asm("cvt.rna.tf32.f32 %0, %1;" : "=r"(r) : "f"(x));
    return r;
}

__device__ __forceinline__ void mma_tf32(float c[4],
                                         unsigned a0, unsigned a1, unsigned a2, unsigned a3,
                                         unsigned b0, unsigned b1) {
    asm volatile(
        "mma.sync.aligned.m16n8k8.row.col.f32.tf32.tf32.f32 "
        "{%0,%1,%2,%3}, {%4,%5,%6,%7}, {%8,%9}, {%0,%1,%2,%3};"
        : "+f"(c[0]), "+f"(c[1]), "+f"(c[2]), "+f"(c[3])
        : "r"(a0), "r"(a1), "r"(a2), "r"(a3), "r"(b0), "r"(b1));
}

// FMA-pipe exp (no MUFU): exp(x) for x <= 0, rel err ~3e-6.
__device__ __forceinline__ float fexp(float x) {
    x = fmaxf(x, -80.f);
    float u = x * 1.4426950408889634f;
    float t = u + 12582912.f;                       // round-to-nearest via magic
    int   i = __float_as_int(t) - 0x4B400000;
    float f = u - (t - 12582912.f);                 // f in [-0.5, 0.5]
    float p = fmaf(f, 0.0013333558f, 0.0096181291f);
    p = fmaf(f, p, 0.055504109f);
    p = fmaf(f, p, 0.24022651f);
    p = fmaf(f, p, 0.69314718f);
    p = fmaf(f, p, 1.0f);
    return p * __int_as_float((i + 127) << 23);
}

__device__ __forceinline__ void cp16(uint32_t saddr, const void* gp) {
    asm volatile("cp.async.cg.shared.global [%0], [%1], 16;"
                 :: "r"(saddr), "l"(__cvta_generic_to_global(gp)));
}
__device__ __forceinline__ void cp_commit() {
    asm volatile("cp.async.commit_group;");
}

// ---------------------------------------------------------------------------
// TF32 tensor-core GEMM: out[m][n] = sum_k A[m][k]*W[n][k], K = 576 fixed.
// CTA tile 256x64, 128 threads = 4 warps; warp tile 64x64 (4 m-frags x 8
// n-frags of m16n8k8). BK=16, register prefetch of next k-slab.
// scatter!=0: qkv epilogue -> g_q (pre-scaled) / g_k / g_v, all tf32-rounded.
// ---------------------------------------------------------------------------
#define GS 20   /* smem row stride: 16 + 4 pad; (20g+c)%32 distinct -> no conflicts */
__global__ __launch_bounds__(128) void gemm_tc(
    const float* __restrict__ A, const float* __restrict__ W,
    float* __restrict__ out, int Ndim, int scatter)
{
    __shared__ float As[256 * GS];
    __shared__ float Bs[64 * GS];

    const int tid  = threadIdx.x;
    const int wid  = tid >> 5, lane = tid & 31;
    const int g    = lane >> 2, c = lane & 3;
    const int m0   = blockIdx.y * 256;
    const int n0   = blockIdx.x * 64;

    const int brow = tid >> 1, bq = (tid & 1) * 8;

    float acc[4][8][4];
#pragma unroll
    for (int i = 0; i < 4; i++)
#pragma unroll
        for (int j = 0; j < 8; j++)
#pragma unroll
            for (int e = 0; e < 4; e++) acc[i][j][e] = 0.f;

    float4 av[8], wv[2];
    // initial load k0 = 0
    {
        const float4* Ap0 = (const float4*)(A + (size_t)(m0 + tid) * 576);
        const float4* Ap1 = (const float4*)(A + (size_t)(m0 + tid + 128) * 576);
        const float4* Wp  = (const float4*)(W + (size_t)(n0 + brow) * 576 + bq);
#pragma unroll
        for (int q = 0; q < 4; q++) { av[q] = Ap0[q]; av[4 + q] = Ap1[q]; }
        wv[0] = Wp[0]; wv[1] = Wp[1];
    }

    for (int k0 = 0; k0 < 576; k0 += 16) {
        __syncthreads();
        // store (with tf32 rounding)
#pragma unroll
        for (int half = 0; half < 2; half++) {
            const int r = tid + half * 128;
#pragma unroll
            for (int q = 0; q < 4; q++) {
                float4 v = av[half * 4 + q];
                float4 s;
                s.x = __uint_as_float(f2tf(v.x));
                s.y = __uint_as_float(f2tf(v.y));
                s.z = __uint_as_float(f2tf(v.z));
                s.w = __uint_as_float(f2tf(v.w));
                *(float4*)&As[r * GS + q * 4] = s;
            }
        }
#pragma unroll
        for (int q = 0; q < 2; q++) {
            float4 v = wv[q];
            float4 s;
            s.x = __uint_as_float(f2tf(v.x));
            s.y = __uint_as_float(f2tf(v.y));
            s.z = __uint_as_float(f2tf(v.z));
            s.w = __uint_as_float(f2tf(v.w));
            *(float4*)&Bs[brow * GS + bq + q * 4] = s;
        }
        __syncthreads();

        // prefetch next k-slab (overlaps with compute below)
        if (k0 + 16 < 576) {
            const int kn = k0 + 16;
            const float4* Ap0 = (const float4*)(A + (size_t)(m0 + tid) * 576 + kn);
            const float4* Ap1 = (const float4*)(A + (size_t)(m0 + tid + 128) * 576 + kn);
            const float4* Wp  = (const float4*)(W + (size_t)(n0 + brow) * 576 + kn + bq);
#pragma unroll
            for (int q = 0; q < 4; q++) { av[q] = Ap0[q]; av[4 + q] = Ap1[q]; }
            wv[0] = Wp[0]; wv[1] = Wp[1];
        }

        // compute 2 k-steps
#pragma unroll
        for (int kk = 0; kk < 2; kk++) {
            const int kb = kk * 8;
            unsigned a[4][4];
#pragma unroll
            for (int i = 0; i < 4; i++) {
                const int mr = wid * 64 + i * 16;
                a[i][0] = __float_as_uint(As[(mr + g) * GS + kb + c]);
                a[i][1] = __float_as_uint(As[(mr + g + 8) * GS + kb + c]);
                a[i][2] = __float_as_uint(As[(mr + g) * GS + kb + c + 4]);
                a[i][3] = __float_as_uint(As[(mr + g + 8) * GS + kb + c + 4]);
            }
#pragma unroll
            for (int j = 0; j < 8; j++) {
                const int nc = j * 8;
                unsigned b0 = __float_as_uint(Bs[(nc + g) * GS + kb + c]);
                unsigned b1 = __float_as_uint(Bs[(nc + g) * GS + kb + c + 4]);
#pragma unroll
                for (int i = 0; i < 4; i++)
                    mma_tf32(acc[i][j], a[i][0], a[i][1], a[i][2], a[i][3], b0, b1);
            }
        }
    }

    const float qscale = 0.14433756729740643f;  // 1/sqrt(48)
#pragma unroll
    for (int i = 0; i < 4; i++) {
#pragma unroll
        for (int j = 0; j < 8; j++) {
            const int col = n0 + j * 8 + 2 * c;
#pragma unroll
            for (int half = 0; half < 2; half++) {
                const int m = m0 + wid * 64 + i * 16 + g + half * 8;
                float v0 = acc[i][j][half * 2 + 0];
                float v1 = acc[i][j][half * 2 + 1];
                if (scatter) {
                    const int b = m >> 11, t = m & 2047;
                    const int which = col / CC;
                    const int cc = col - which * CC;
                    const int h = cc / DD, d = cc - h * DD;
                    float* dst = (which == 0) ? g_q : (which == 1) ? g_k : g_v;
                    if (which == 0) { v0 *= qscale; v1 *= qscale; }
                    float2 st;
                    st.x = __uint_as_float(f2tf(v0));
                    st.y = __uint_as_float(f2tf(v1));
                    *(float2*)&dst[(((size_t)b * HH + h) * TT + t) * DD + d] = st;
                } else {
                    float2 st; st.x = v0; st.y = v1;
                    *(float2*)&out[(size_t)m * Ndim + col] = st;
                }
            }
        }
    }
}

// ---------------------------------------------------------------------------
// Flash attention, tf32 tensor cores. BR=128, BC=64, 128 threads = 4 warps.
// Warp w owns rows w*32 .. w*32+31 (2 m16 fragments). K/V double-buffered in
// dynamic smem via cp.async. P staged per-warp (stride 68) with STS.64.
// ---------------------------------------------------------------------------
#define AK 52   /* K row stride (>=48), 52%32=20 -> conflict-free frag reads */
#define AV 56   /* V row stride, 56%32=24 -> conflict-free */
#define AP 68   /* P row stride */
#define OFF_K0 0
#define OFF_K1 (64*AK)
#define OFF_V0 (2*64*AK)
#define OFF_V1 (2*64*AK + 64*AV)
#define OFF_P  (2*64*AK + 2*64*AV)
#define ASM_FLOATS (OFF_P + 128*AP)
#define ASM_BYTES  (ASM_FLOATS * 4)

extern __shared__ float sm_attn[];

__global__ __launch_bounds__(128) void attn_tc(float* __restrict__ ypre)
{
    const int rb = blockIdx.x, h = blockIdx.y, b = blockIdx.z;
    const int tid = threadIdx.x, wid = tid >> 5, lane = tid & 31;
    const int g = lane >> 2, c = lane & 3;
    const int t0 = rb * 128;
    const int nblk = 2 * rb + 2;
    const size_t bh = ((size_t)b * HH + h) * TT;

    // Q a-fragments for both m-frags (values pre-scaled & tf32-rounded)
    unsigned qa[2][6][4];
#pragma unroll
    for (int mi = 0; mi < 2; mi++) {
        const float* Qb = g_q + (bh + t0 + wid * 32 + mi * 16) * DD;
#pragma unroll
        for (int k = 0; k < 6; k++) {
            qa[mi][k][0] = __float_as_uint(Qb[(g) * DD + k * 8 + c]);
            qa[mi][k][1] = __float_as_uint(Qb[(g + 8) * DD + k * 8 + c]);
            qa[mi][k][2] = __float_as_uint(Qb[(g) * DD + k * 8 + c + 4]);
            qa[mi][k][3] = __float_as_uint(Qb[(g + 8) * DD + k * 8 + c + 4]);
        }
    }

    float o[2][6][4];
#pragma unroll
    for (int mi = 0; mi < 2; mi++)
#pragma unroll
        for (int nf = 0; nf < 6; nf++)
#pragma unroll
            for (int e = 0; e < 4; e++) o[mi][nf][e] = 0.f;
    float mA[2] = {-1e30f, -1e30f}, mB[2] = {-1e30f, -1e30f};
    float lA[2] = {0.f, 0.f},       lB[2] = {0.f, 0.f};

    const int ldrow = tid >> 1, ldd = (tid & 1) * 24;
    const uint32_t smbase = (uint32_t)__cvta_generic_to_shared(sm_attn);

    // issue jb = 0 into buffer 0
    {
        const float* Kp = g_k + (bh + ldrow) * DD + ldd;
        const float* Vp = g_v + (bh + ldrow) * DD + ldd;
        const uint32_t kd = smbase + (OFF_K0 + ldrow * AK + ldd) * 4;
        const uint32_t vd = smbase + (OFF_V0 + ldrow * AV + ldd) * 4;
#pragma unroll
        for (int i = 0; i < 6; i++) {
            cp16(kd + i * 16, Kp + i * 4);
            cp16(vd + i * 16, Vp + i * 4);
        }
        cp_commit();
    }

    for (int jb = 0; jb < nblk; jb++) {
        const int cur = jb & 1;
        if (jb + 1 < nblk) {
            const float* Kp = g_k + (bh + (size_t)(jb + 1) * 64 + ldrow) * DD + ldd;
            const float* Vp = g_v + (bh + (size_t)(jb + 1) * 64 + ldrow) * DD + ldd;
            const uint32_t kd = smbase + (((jb + 1) & 1 ? OFF_K1 : OFF_K0) + ldrow * AK + ldd) * 4;
            const uint32_t vd = smbase + (((jb + 1) & 1 ? OFF_V1 : OFF_V0) + ldrow * AV + ldd) * 4;
#pragma unroll
            for (int i = 0; i < 6; i++) {
                cp16(kd + i * 16, Kp + i * 4);
                cp16(vd + i * 16, Vp + i * 4);
            }
            cp_commit();
            asm volatile("cp.async.wait_group 1;");
        } else {
            asm volatile("cp.async.wait_group 0;");
        }
        __syncthreads();

        const float* Ks = sm_attn + (cur ? OFF_K1 : OFF_K0);
        const float* Vs = sm_attn + (cur ? OFF_V1 : OFF_V0);

        // S = Q K^T, both m-frags share K b-frags
        float s[2][8][4];
#pragma unroll
        for (int mi = 0; mi < 2; mi++)
#pragma unroll
            for (int f = 0; f < 8; f++)
#pragma unroll
                for (int e = 0; e < 4; e++) s[mi][f][e] = 0.f;
#pragma unroll
        for (int f = 0; f < 8; f++) {
#pragma unroll
            for (int k = 0; k < 6; k++) {
                unsigned b0 = __float_as_uint(Ks[(f * 8 + g) * AK + k * 8 + c]);
                unsigned b1 = __float_as_uint(Ks[(f * 8 + g) * AK + k * 8 + c + 4]);
                mma_tf32(s[0][f], qa[0][k][0], qa[0][k][1], qa[0][k][2], qa[0][k][3], b0, b1);
                mma_tf32(s[1][f], qa[1][k][0], qa[1][k][1], qa[1][k][2], qa[1][k][3], b0, b1);
            }
        }

        // causal mask (only the last two key-blocks can clip)
        if (jb >= 2 * rb) {
            const int off = (jb - 2 * rb) * 64;   // 0 or 64
#pragma unroll
            for (int mi = 0; mi < 2; mi++) {
                const int ra  = wid * 32 + mi * 16 + g - off;
                const int ra8 = ra + 8;
#pragma unroll
                for (int f = 0; f < 8; f++) {
                    const int col = f * 8 + 2 * c;
                    if (col > ra)       s[mi][f][0] = -1e30f;
                    if (col + 1 > ra)   s[mi][f][1] = -1e30f;
                    if (col > ra8)      s[mi][f][2] = -1e30f;
                    if (col + 1 > ra8)  s[mi][f][3] = -1e30f;
                }
            }
        }

        // online softmax per m-frag (FMA-pipe exp)
#pragma unroll
        for (int mi = 0; mi < 2; mi++) {
            float mja = -1e30f, mjb = -1e30f;
#pragma unroll
            for (int f = 0; f < 8; f++) {
                mja = fmaxf(mja, fmaxf(s[mi][f][0], s[mi][f][1]));
                mjb = fmaxf(mjb, fmaxf(s[mi][f][2], s[mi][f][3]));
            }
            mja = fmaxf(mja, __shfl_xor_sync(0xffffffffu, mja, 1));
            mja = fmaxf(mja, __shfl_xor_sync(0xffffffffu, mja, 2));
            mjb = fmaxf(mjb, __shfl_xor_sync(0xffffffffu, mjb, 1));
            mjb = fmaxf(mjb, __shfl_xor_sync(0xffffffffu, mjb, 2));
            const float mna = fmaxf(mA[mi], mja), mnb = fmaxf(mB[mi], mjb);
            const float ca = fexp(mA[mi] - mna), cb = fexp(mB[mi] - mnb);
            float psa = 0.f, psb = 0.f;
#pragma unroll
            for (int f = 0; f < 8; f++) {
                s[mi][f][0] = fexp(s[mi][f][0] - mna); psa += s[mi][f][0];
                s[mi][f][1] = fexp(s[mi][f][1] - mna); psa += s[mi][f][1];
                s[mi][f][2] = fexp(s[mi][f][2] - mnb); psb += s[mi][f][2];
                s[mi][f][3] = fexp(s[mi][f][3] - mnb); psb += s[mi][f][3];
            }
            mA[mi] = mna; mB[mi] = mnb;
            lA[mi] = lA[mi] * ca + psa;
            lB[mi] = lB[mi] * cb + psb;
#pragma unroll
            for (int nf = 0; nf < 6; nf++) {
                o[mi][nf][0] *= ca; o[mi][nf][1] *= ca;
                o[mi][nf][2] *= cb; o[mi][nf][3] *= cb;
            }
        }

        // stage P (tf32) through per-warp smem slab, STS.64
        float* Ps = sm_attn + OFF_P;
#pragma unroll
        for (int mi = 0; mi < 2; mi++) {
            const int pr = wid * 32 + mi * 16 + g;
#pragma unroll
            for (int f = 0; f < 8; f++) {
                const int col = f * 8 + 2 * c;
                float2 pa, pb;
                pa.x = __uint_as_float(f2tf(s[mi][f][0]));
                pa.y = __uint_as_float(f2tf(s[mi][f][1]));
                pb.x = __uint_as_float(f2tf(s[mi][f][2]));
                pb.y = __uint_as_float(f2tf(s[mi][f][3]));
                *(float2*)&Ps[pr * AP + col] = pa;
                *(float2*)&Ps[(pr + 8) * AP + col] = pb;
            }
        }
        __syncwarp();

        // O += P V   (8 key-steps, 6 d-frags; V b-frags shared across m-frags)
#pragma unroll
        for (int k = 0; k < 8; k++) {
            unsigned pa[2][4];
#pragma unroll
            for (int mi = 0; mi < 2; mi++) {
                const int pr = wid * 32 + mi * 16;
                pa[mi][0] = __float_as_uint(Ps[(pr + g) * AP + k * 8 + c]);
                pa[mi][1] = __float_as_uint(Ps[(pr + g + 8) * AP + k * 8 + c]);
                pa[mi][2] = __float_as_uint(Ps[(pr + g) * AP + k * 8 + c + 4]);
                pa[mi][3] = __float_as_uint(Ps[(pr + g + 8) * AP + k * 8 + c + 4]);
            }
#pragma unroll
            for (int nf = 0; nf < 6; nf++) {
                unsigned b0 = __float_as_uint(Vs[(k * 8 + c) * AV + nf * 8 + g]);
                unsigned b1 = __float_as_uint(Vs[(k * 8 + c + 4) * AV + nf * 8 + g]);
                mma_tf32(o[0][nf], pa[0][0], pa[0][1], pa[0][2], pa[0][3], b0, b1);
                mma_tf32(o[1][nf], pa[1][0], pa[1][1], pa[1][2], pa[1][3], b0, b1);
            }
        }
        __syncthreads();
    }

    // finalize
#pragma unroll
    for (int mi = 0; mi < 2; mi++) {
        float la = lA[mi], lb = lB[mi];
        la += __shfl_xor_sync(0xffffffffu, la, 1);
        la += __shfl_xor_sync(0xffffffffu, la, 2);
        lb += __shfl_xor_sync(0xffffffffu, lb, 1);
        lb += __shfl_xor_sync(0xffffffffu, lb, 2);
        const float ia = 1.f / la, ib = 1.f / lb;
        const int ra = t0 + wid * 32 + mi * 16 + g;
        float* ya = ypre + ((size_t)b * TT + ra) * CC + h * DD;
        float* yb = ypre + ((size_t)b * TT + ra + 8) * CC + h * DD;
#pragma unroll
        for (int nf = 0; nf < 6; nf++) {
            const int d = nf * 8 + 2 * c;
            float2 sa; sa.x = o[mi][nf][0] * ia; sa.y = o[mi][nf][1] * ia;
            float2 sb; sb.x = o[mi][nf][2] * ib; sb.y = o[mi][nf][3] * ib;
            *(float2*)&ya[d] = sa;
            *(float2*)&yb[d] = sb;
        }
    }
}

extern "C" void kernel_launch(void* const* d_in, const int* in_sizes, int n_in,
                              void* d_out, int out_size)
{
    (void)in_sizes; (void)n_in; (void)out_size;
    const float* x      = (const float*)d_in[0];
    const float* w_qkv  = (const float*)d_in[1];
    const float* w_proj = (const float*)d_in[2];
    float* out = (float*)d_out;

    float* yptr = nullptr;
    cudaGetSymbolAddress((void**)&yptr, g_y);

    cudaFuncSetAttribute(attn_tc, cudaFuncAttributeMaxDynamicSharedMemorySize,
                         ASM_BYTES);

    // 1) qkv GEMM (tf32 TC) + scatter into q/k/v [B,H,T,D], pre-scaled/rounded
    {
        dim3 grid(NQKV / 64, MM / 256);
        gemm_tc<<<grid, 128>>>(x, w_qkv, nullptr, NQKV, 1);
    }
    // 2) causal flash attention (tf32 TC) -> g_y [B,T,C]
    {
        dim3 grid(TT / 128, HH, BB);
        attn_tc<<<grid, 128, ASM_BYTES>>>(yptr);
    }
    // 3) output projection (tf32 TC)
    {
        dim3 grid(CC / 64, MM / 256);
        gemm_tc<<<grid, 128>>>(yptr, w_proj, out, CC, 0);
    }
}

// round 5
// speedup vs baseline: 1.2623x; 1.2623x over previous
#include <cuda_runtime.h>
#include <cstdint>

#define BB 4
#define TT 2048
#define CC 576
#define HH 12
#define DD 48
#define MM (BB*TT)       /* 8192 */
#define NQKV (3*CC)      /* 1728 */

// Scratch (device globals: allocation-free). q/k/v stored pre-rounded to tf32
// (q additionally pre-scaled by 1/sqrt(48)). y stored pre-rounded by attention.
__device__ float g_q[BB*HH*TT*DD];
__device__ float g_k[BB*HH*TT*DD];
__device__ float g_v[BB*HH*TT*DD];
__device__ float g_y[BB*TT*CC];
__device__ float g_xr[MM*CC];       // tf32-rounded x
__device__ float g_wqr[NQKV*CC];    // tf32-rounded w_qkv
__device__ float g_wpr[CC*CC];      // tf32-rounded w_proj

// ---------------------------------------------------------------------------
// helpers
// ---------------------------------------------------------------------------
__device__ __forceinline__ unsigned f2tf(float x) {
    unsigned r;
    asm("cvt.rna.tf32.f32 %0, %1;" : "=r"(r) : "f"(x));
    return r;
}

__device__ __forceinline__ void mma_tf32(float c[4],
                                         unsigned a0, unsigned a1, unsigned a2, unsigned a3,
                                         unsigned b0, unsigned b1) {
    asm volatile(
        "mma.sync.aligned.m16n8k8.row.col.f32.tf32.tf32.f32 "
        "{%0,%1,%2,%3}, {%4,%5,%6,%7}, {%8,%9}, {%0,%1,%2,%3};"
        : "+f"(c[0]), "+f"(c[1]), "+f"(c[2]), "+f"(c[3])
        : "r"(a0), "r"(a1), "r"(a2), "r"(a3), "r"(b0), "r"(b1));
}

// FMA-pipe exp (no MUFU): exp(x) for x <= 0, rel err ~3e-6.
__device__ __forceinline__ float fexp(float x) {
    x = fmaxf(x, -80.f);
    float u = x * 1.4426950408889634f;
    float t = u + 12582912.f;
    int   i = __float_as_int(t) - 0x4B400000;
    float f = u - (t - 12582912.f);
    float p = fmaf(f, 0.0013333558f, 0.0096181291f);
    p = fmaf(f, p, 0.055504109f);
    p = fmaf(f, p, 0.24022651f);
    p = fmaf(f, p, 0.69314718f);
    p = fmaf(f, p, 1.0f);
    return p * __int_as_float((i + 127) << 23);
}

__device__ __forceinline__ void cp16(uint32_t saddr, const void* gp) {
    asm volatile("cp.async.cg.shared.global [%0], [%1], 16;"
                 :: "r"(saddr), "l"(__cvta_generic_to_global(gp)));
}
__device__ __forceinline__ void cp_commit() {
    asm volatile("cp.async.commit_group;");
}

// ---------------------------------------------------------------------------
// prep: elementwise tf32 rounding (rna) of GEMM inputs
// ---------------------------------------------------------------------------
__global__ void round_tf32(const float* __restrict__ src, float* __restrict__ dst, int n4)
{
    int i = blockIdx.x * blockDim.x + threadIdx.x;
    if (i < n4) {
        float4 v = ((const float4*)src)[i];
        float4 s;
        s.x = __uint_as_float(f2tf(v.x));
        s.y = __uint_as_float(f2tf(v.y));
        s.z = __uint_as_float(f2tf(v.z));
        s.w = __uint_as_float(f2tf(v.w));
        ((float4*)dst)[i] = s;
    }
}

// ---------------------------------------------------------------------------
// TF32 tensor-core GEMM: out[m][n] = sum_k A[m][k]*W[n][k], K = 576 fixed.
// A, W must be PRE-ROUNDED to tf32. CTA 256x64, 128 threads = 4 warps; warp
// tile 64x64. BK=32, cp.async double-buffered (no register staging).
// scatter!=0: qkv epilogue -> g_q (pre-scaled) / g_k / g_v, tf32-rounded.
// ---------------------------------------------------------------------------
#define GS 36                     /* smem row stride: 32 + 4 pad, 16B aligned */
#define GA_FLOATS (256*GS)
#define GB_FLOATS (64*GS)
#define GBUF (GA_FLOATS + GB_FLOATS)
#define GSM_BYTES (2*GBUF*4)

extern __shared__ float sm_dyn[];

__global__ __launch_bounds__(128) void gemm_tc(
    const float* __restrict__ A, const float* __restrict__ W,
    float* __restrict__ out, int Ndim, int scatter)
{
    const int tid  = threadIdx.x;
    const int wid  = tid >> 5, lane = tid & 31;
    const int g    = lane >> 2, c = lane & 3;
    const int m0   = blockIdx.y * 256;
    const int n0   = blockIdx.x * 64;
    const uint32_t smbase = (uint32_t)__cvta_generic_to_shared(sm_dyn);

    float acc[4][8][4];
#pragma unroll
    for (int i = 0; i < 4; i++)
#pragma unroll
        for (int j = 0; j < 8; j++)
#pragma unroll
            for (int e = 0; e < 4; e++) acc[i][j][e] = 0.f;

    auto issue = [&](int it) {
        const int k0 = it * 32;
        const uint32_t base = smbase + (uint32_t)(it & 1) * (GBUF * 4);
#pragma unroll
        for (int i = 0; i < 16; i++) {
            const int ch = tid + i * 128;
            const int row = ch >> 3, cq = ch & 7;
            cp16(base + (uint32_t)(row * GS + cq * 4) * 4,
                 A + (size_t)(m0 + row) * 576 + k0 + cq * 4);
        }
        const uint32_t bb = base + GA_FLOATS * 4;
#pragma unroll
        for (int i = 0; i < 4; i++) {
            const int ch = tid + i * 128;
            const int row = ch >> 3, cq = ch & 7;
            cp16(bb + (uint32_t)(row * GS + cq * 4) * 4,
                 W + (size_t)(n0 + row) * 576 + k0 + cq * 4);
        }
        cp_commit();
    };

    issue(0);
    for (int it = 0; it < 18; it++) {
        if (it + 1 < 18) {
            issue(it + 1);
            asm volatile("cp.async.wait_group 1;");
        } else {
            asm volatile("cp.async.wait_group 0;");
        }
        __syncthreads();
        const float* As = sm_dyn + (it & 1) * GBUF;
        const float* Bs = As + GA_FLOATS;

#pragma unroll
        for (int kk = 0; kk < 4; kk++) {
            const int kb = kk * 8;
            unsigned a[4][4];
#pragma unroll
            for (int i = 0; i < 4; i++) {
                const int mr = wid * 64 + i * 16;
                a[i][0] = __float_as_uint(As[(mr + g) * GS + kb + c]);
                a[i][1] = __float_as_uint(As[(mr + g + 8) * GS + kb + c]);
                a[i][2] = __float_as_uint(As[(mr + g) * GS + kb + c + 4]);
                a[i][3] = __float_as_uint(As[(mr + g + 8) * GS + kb + c + 4]);
            }
#pragma unroll
            for (int j = 0; j < 8; j++) {
                unsigned b0 = __float_as_uint(Bs[(j * 8 + g) * GS + kb + c]);
                unsigned b1 = __float_as_uint(Bs[(j * 8 + g) * GS + kb + c + 4]);
#pragma unroll
                for (int i = 0; i < 4; i++)
                    mma_tf32(acc[i][j], a[i][0], a[i][1], a[i][2], a[i][3], b0, b1);
            }
        }
        __syncthreads();
    }

    const float qscale = 0.14433756729740643f;  // 1/sqrt(48)
#pragma unroll
    for (int i = 0; i < 4; i++) {
#pragma unroll
        for (int j = 0; j < 8; j++) {
            const int col = n0 + j * 8 + 2 * c;
#pragma unroll
            for (int half = 0; half < 2; half++) {
                const int m = m0 + wid * 64 + i * 16 + g + half * 8;
                float v0 = acc[i][j][half * 2 + 0];
                float v1 = acc[i][j][half * 2 + 1];
                if (scatter) {
                    const int b = m >> 11, t = m & 2047;
                    const int which = col / CC;
                    const int cc = col - which * CC;
                    const int h = cc / DD, d = cc - h * DD;
                    float* dst = (which == 0) ? g_q : (which == 1) ? g_k : g_v;
                    if (which == 0) { v0 *= qscale; v1 *= qscale; }
                    float2 st;
                    st.x = __uint_as_float(f2tf(v0));
                    st.y = __uint_as_float(f2tf(v1));
                    *(float2*)&dst[(((size_t)b * HH + h) * TT + t) * DD + d] = st;
                } else {
                    float2 st; st.x = v0; st.y = v1;
                    *(float2*)&out[(size_t)m * Ndim + col] = st;
                }
            }
        }
    }
}

// ---------------------------------------------------------------------------
// Flash attention, tf32 tensor cores. BR=128, BC=64, 128 threads = 4 warps.
// Warp w owns rows w*32..w*32+31 (2 m16 fragments). K/V double-buffered via
// cp.async. P re-fragmentation for P·V done with warp shuffles (no smem P).
// Heavy CTAs (large rb) launch first via reversed blockIdx.x.
// ---------------------------------------------------------------------------
#define AK 52
#define AV 56
#define OFF_K0 0
#define OFF_K1 (64*AK)
#define OFF_V0 (2*64*AK)
#define OFF_V1 (2*64*AK + 64*AV)
#define ASM_FLOATS (2*64*AK + 2*64*AV)
#define ASM_BYTES  (ASM_FLOATS * 4)

__global__ __launch_bounds__(128) void attn_tc(float* __restrict__ ypre)
{
    const int rb = (gridDim.x - 1) - blockIdx.x;   // heavy blocks first
    const int h = blockIdx.y, b = blockIdx.z;
    const int tid = threadIdx.x, wid = tid >> 5, lane = tid & 31;
    const int g = lane >> 2, c = lane & 3;
    const int t0 = rb * 128;
    const int nblk = 2 * rb + 2;
    const size_t bh = ((size_t)b * HH + h) * TT;

    unsigned qa[2][6][4];
#pragma unroll
    for (int mi = 0; mi < 2; mi++) {
        const float* Qb = g_q + (bh + t0 + wid * 32 + mi * 16) * DD;
#pragma unroll
        for (int k = 0; k < 6; k++) {
            qa[mi][k][0] = __float_as_uint(Qb[(g) * DD + k * 8 + c]);
            qa[mi][k][1] = __float_as_uint(Qb[(g + 8) * DD + k * 8 + c]);
            qa[mi][k][2] = __float_as_uint(Qb[(g) * DD + k * 8 + c + 4]);
            qa[mi][k][3] = __float_as_uint(Qb[(g + 8) * DD + k * 8 + c + 4]);
        }
    }

    float o[2][6][4];
#pragma unroll
    for (int mi = 0; mi < 2; mi++)
#pragma unroll
        for (int nf = 0; nf < 6; nf++)
#pragma unroll
            for (int e = 0; e < 4; e++) o[mi][nf][e] = 0.f;
    float mA[2] = {-1e30f, -1e30f}, mB[2] = {-1e30f, -1e30f};
    float lA[2] = {0.f, 0.f},       lB[2] = {0.f, 0.f};

    const int ldrow = tid >> 1, ldd = (tid & 1) * 24;
    const uint32_t smbase = (uint32_t)__cvta_generic_to_shared(sm_dyn);
    const int srcA = (lane & ~3) | (c >> 1);       // P-shuffle source lanes
    const int srcB = srcA + 2;
    const bool odd = (c & 1);

    {
        const float* Kp = g_k + (bh + ldrow) * DD + ldd;
        const float* Vp = g_v + (bh + ldrow) * DD + ldd;
        const uint32_t kd = smbase + (OFF_K0 + ldrow * AK + ldd) * 4;
        const uint32_t vd = smbase + (OFF_V0 + ldrow * AV + ldd) * 4;
#pragma unroll
        for (int i = 0; i < 6; i++) {
            cp16(kd + i * 16, Kp + i * 4);
            cp16(vd + i * 16, Vp + i * 4);
        }
        cp_commit();
    }

    for (int jb = 0; jb < nblk; jb++) {
        const int cur = jb & 1;
        if (jb + 1 < nblk) {
            const float* Kp = g_k + (bh + (size_t)(jb + 1) * 64 + ldrow) * DD + ldd;
            const float* Vp = g_v + (bh + (size_t)(jb + 1) * 64 + ldrow) * DD + ldd;
            const uint32_t kd = smbase + (((jb + 1) & 1 ? OFF_K1 : OFF_K0) + ldrow * AK + ldd) * 4;
            const uint32_t vd = smbase + (((jb + 1) & 1 ? OFF_V1 : OFF_V0) + ldrow * AV + ldd) * 4;
#pragma unroll
            for (int i = 0; i < 6; i++) {
                cp16(kd + i * 16, Kp + i * 4);
                cp16(vd + i * 16, Vp + i * 4);
            }
            cp_commit();
            asm volatile("cp.async.wait_group 1;");
        } else {
            asm volatile("cp.async.wait_group 0;");
        }
        __syncthreads();

        const float* Ks = sm_dyn + (cur ? OFF_K1 : OFF_K0);
        const float* Vs = sm_dyn + (cur ? OFF_V1 : OFF_V0);

        // S = Q K^T
        float s[2][8][4];
#pragma unroll
        for (int mi = 0; mi < 2; mi++)
#pragma unroll
            for (int f = 0; f < 8; f++)
#pragma unroll
                for (int e = 0; e < 4; e++) s[mi][f][e] = 0.f;
#pragma unroll
        for (int f = 0; f < 8; f++) {
#pragma unroll
            for (int k = 0; k < 6; k++) {
                unsigned b0 = __float_as_uint(Ks[(f * 8 + g) * AK + k * 8 + c]);
                unsigned b1 = __float_as_uint(Ks[(f * 8 + g) * AK + k * 8 + c + 4]);
                mma_tf32(s[0][f], qa[0][k][0], qa[0][k][1], qa[0][k][2], qa[0][k][3], b0, b1);
                mma_tf32(s[1][f], qa[1][k][0], qa[1][k][1], qa[1][k][2], qa[1][k][3], b0, b1);
            }
        }

        if (jb >= 2 * rb) {
            const int off = (jb - 2 * rb) * 64;
#pragma unroll
            for (int mi = 0; mi < 2; mi++) {
                const int ra  = wid * 32 + mi * 16 + g - off;
                const int ra8 = ra + 8;
#pragma unroll
                for (int f = 0; f < 8; f++) {
                    const int col = f * 8 + 2 * c;
                    if (col > ra)       s[mi][f][0] = -1e30f;
                    if (col + 1 > ra)   s[mi][f][1] = -1e30f;
                    if (col > ra8)      s[mi][f][2] = -1e30f;
                    if (col + 1 > ra8)  s[mi][f][3] = -1e30f;
                }
            }
        }

        // online softmax (FMA-pipe exp)
#pragma unroll
        for (int mi = 0; mi < 2; mi++) {
            float mja = -1e30f, mjb = -1e30f;
#pragma unroll
            for (int f = 0; f < 8; f++) {
                mja = fmaxf(mja, fmaxf(s[mi][f][0], s[mi][f][1]));
                mjb = fmaxf(mjb, fmaxf(s[mi][f][2], s[mi][f][3]));
            }
            mja = fmaxf(mja, __shfl_xor_sync(0xffffffffu, mja, 1));
            mja = fmaxf(mja, __shfl_xor_sync(0xffffffffu, mja, 2));
            mjb = fmaxf(mjb, __shfl_xor_sync(0xffffffffu, mjb, 1));
            mjb = fmaxf(mjb, __shfl_xor_sync(0xffffffffu, mjb, 2));
            const float mna = fmaxf(mA[mi], mja), mnb = fmaxf(mB[mi], mjb);
            const float ca = fexp(mA[mi] - mna), cb = fexp(mB[mi] - mnb);
            float psa = 0.f, psb = 0.f;
#pragma unroll
            for (int f = 0; f < 8; f++) {
                s[mi][f][0] = fexp(s[mi][f][0] - mna); psa += s[mi][f][0];
                s[mi][f][1] = fexp(s[mi][f][1] - mna); psa += s[mi][f][1];
                s[mi][f][2] = fexp(s[mi][f][2] - mnb); psb += s[mi][f][2];
                s[mi][f][3] = fexp(s[mi][f][3] - mnb); psb += s[mi][f][3];
            }
            mA[mi] = mna; mB[mi] = mnb;
            lA[mi] = lA[mi] * ca + psa;
            lB[mi] = lB[mi] * cb + psb;
#pragma unroll
            for (int nf = 0; nf < 6; nf++) {
                o[nf == 0 ? mi : mi][nf][0] *= ca; o[mi][nf][1] *= ca;
                o[mi][nf][2] *= cb; o[mi][nf][3] *= cb;
            }
        }

        // O += P V  — P a-frags built from S c-frags via 4-lane shuffles.
        // a0 = P[g, k8+c]   <- lane srcA, elem (c&1)   of s[k][0..1]
        // a1 = P[g+8, k8+c] <- lane srcA, elem 2+(c&1)
        // a2/a3: same from lane srcB (cols k8+c+4).
#pragma unroll
        for (int k = 0; k < 8; k++) {
            unsigned pa[2][4];
#pragma unroll
            for (int mi = 0; mi < 2; mi++) {
                float u0 = __shfl_sync(0xffffffffu, s[mi][k][0], srcA);
                float u1 = __shfl_sync(0xffffffffu, s[mi][k][1], srcA);
                float u2 = __shfl_sync(0xffffffffu, s[mi][k][2], srcA);
                float u3 = __shfl_sync(0xffffffffu, s[mi][k][3], srcA);
                float w0 = __shfl_sync(0xffffffffu, s[mi][k][0], srcB);
                float w1 = __shfl_sync(0xffffffffu, s[mi][k][1], srcB);
                float w2 = __shfl_sync(0xffffffffu, s[mi][k][2], srcB);
                float w3 = __shfl_sync(0xffffffffu, s[mi][k][3], srcB);
                pa[mi][0] = __float_as_uint(odd ? u1 : u0);
                pa[mi][1] = __float_as_uint(odd ? u3 : u2);
                pa[mi][2] = __float_as_uint(odd ? w1 : w0);
                pa[mi][3] = __float_as_uint(odd ? w3 : w2);
            }
#pragma unroll
            for (int nf = 0; nf < 6; nf++) {
                unsigned b0 = __float_as_uint(Vs[(k * 8 + c) * AV + nf * 8 + g]);
                unsigned b1 = __float_as_uint(Vs[(k * 8 + c + 4) * AV + nf * 8 + g]);
                mma_tf32(o[0][nf], pa[0][0], pa[0][1], pa[0][2], pa[0][3], b0, b1);
                mma_tf32(o[1][nf], pa[1][0], pa[1][1], pa[1][2], pa[1][3], b0, b1);
            }
        }
        __syncthreads();
    }

    // finalize (y stored tf32-rounded for the proj GEMM)
#pragma unroll
    for (int mi = 0; mi < 2; mi++) {
        float la = lA[mi], lb = lB[mi];
        la += __shfl_xor_sync(0xffffffffu, la, 1);
        la += __shfl_xor_sync(0xffffffffu, la, 2);
        lb += __shfl_xor_sync(0xffffffffu, lb, 1);
        lb += __shfl_xor_sync(0xffffffffu, lb, 2);
        const float ia = 1.f / la, ib = 1.f / lb;
        const int ra = t0 + wid * 32 + mi * 16 + g;
        float* ya = ypre + ((size_t)b * TT + ra) * CC + h * DD;
        float* yb = ypre + ((size_t)b * TT + ra + 8) * CC + h * DD;
#pragma unroll
        for (int nf = 0; nf < 6; nf++) {
            const int d = nf * 8 + 2 * c;
            float2 sa, sb;
            sa.x = __uint_as_float(f2tf(o[mi][nf][0] * ia));
            sa.y = __uint_as_float(f2tf(o[mi][nf][1] * ia));
            sb.x = __uint_as_float(f2tf(o[mi][nf][2] * ib));
            sb.y = __uint_as_float(f2tf(o[mi][nf][3] * ib));
            *(float2*)&ya[d] = sa;
            *(float2*)&yb[d] = sb;
        }
    }
}

extern "C" void kernel_launch(void* const* d_in, const int* in_sizes, int n_in,
                              void* d_out, int out_size)
{
    (void)in_sizes; (void)n_in; (void)out_size;
    const float* x      = (const float*)d_in[0];
    const float* w_qkv  = (const float*)d_in[1];
    const float* w_proj = (const float*)d_in[2];
    float* out = (float*)d_out;

    float *yptr = nullptr, *xr = nullptr, *wqr = nullptr, *wpr = nullptr;
    cudaGetSymbolAddress((void**)&yptr, g_y);
    cudaGetSymbolAddress((void**)&xr,  g_xr);
    cudaGetSymbolAddress((void**)&wqr, g_wqr);
    cudaGetSymbolAddress((void**)&wpr, g_wpr);

    cudaFuncSetAttribute(gemm_tc, cudaFuncAttributeMaxDynamicSharedMemorySize, GSM_BYTES);
    cudaFuncSetAttribute(attn_tc, cudaFuncAttributeMaxDynamicSharedMemorySize, ASM_BYTES);

    // 0) pre-round GEMM inputs to tf32 (rna)
    round_tf32<<<(MM*CC/4 + 255)/256, 256>>>(x, xr, MM*CC/4);
    round_tf32<<<(NQKV*CC/4 + 255)/256, 256>>>(w_qkv, wqr, NQKV*CC/4);
    round_tf32<<<(CC*CC/4 + 255)/256, 256>>>(w_proj, wpr, CC*CC/4);

    // 1) qkv GEMM -> scatter q/k/v [B,H,T,D]
    {
        dim3 grid(NQKV / 64, MM / 256);
        gemm_tc<<<grid, 128, GSM_BYTES>>>(xr, wqr, nullptr, NQKV, 1);
    }
    // 2) causal flash attention -> g_y [B,T,C] (tf32-rounded)
    {
        dim3 grid(TT / 128, HH, BB);
        attn_tc<<<grid, 128, ASM_BYTES>>>(yptr);
    }
    // 3) output projection
    {
        dim3 grid(CC / 64, MM / 256);
        gemm_tc<<<grid, 128, GSM_BYTES>>>(yptr, wpr, out, CC, 0);
    }
}